// round 6
// baseline (speedup 1.0000x reference)
#include <cuda_runtime.h>
#include <math.h>

// Problem constants
#define Bb 2
#define Dd 256
#define Hh 8
#define Tt 128
#define Ff 64
#define Cc 512
#define TEc 512
#define Ss 128
#define NROW (Bb * Tt * Ss)   // 32768
#define BT (Bb * Tt)          // 256

// Scratch (no cudaMalloc allowed)
__device__ float    g_time_proj[BT * Cc];
__device__ float    g_table[256 * Cc];
__device__ unsigned g_act[NROW * Cc];   // tf32 bits
__device__ unsigned g_R[NROW * Cc];     // tf32 bits
__device__ unsigned g_Wtf[Cc * Cc];     // w_out as tf32 bits

// ---------------------------------------------------------------------------
// helpers
// ---------------------------------------------------------------------------
__device__ __forceinline__ unsigned f2tf(float x) {
    unsigned r;
    asm("cvt.rna.tf32.f32 %0, %1;" : "=r"(r) : "f"(x));
    return r;
}
__device__ __forceinline__ float tanh_fast(float x) {
    float y;
    asm("tanh.approx.f32 %0, %1;" : "=f"(y) : "f"(x));
    return y;
}
__device__ __forceinline__ float silu_fast(float x) {
    return x * (0.5f * tanh_fast(0.5f * x) + 0.5f);
}
__device__ __forceinline__ void mma_tf32(float* c, const unsigned* a, const unsigned* b) {
    asm volatile(
        "mma.sync.aligned.m16n8k8.row.col.f32.tf32.tf32.f32 "
        "{%0,%1,%2,%3}, {%4,%5,%6,%7}, {%8,%9}, {%0,%1,%2,%3};"
        : "+f"(c[0]), "+f"(c[1]), "+f"(c[2]), "+f"(c[3])
        : "r"(a[0]), "r"(a[1]), "r"(a[2]), "r"(a[3]),
          "r"(b[0]), "r"(b[1]));
}
__device__ __forceinline__ void cp16(unsigned sdst, const void* gsrc) {
    asm volatile("cp.async.cg.shared.global [%0], [%1], 16;\n"
                 :: "r"(sdst), "l"(gsrc));
}
#define CP_COMMIT() asm volatile("cp.async.commit_group;\n" ::: "memory")
#define CP_WAIT(n)  asm volatile("cp.async.wait_group %0;\n" :: "n"(n) : "memory")

// ---------------------------------------------------------------------------
// K0: distance table (includes b_dist)
// ---------------------------------------------------------------------------
__global__ void k_table(const float* __restrict__ w_dist,
                        const float* __restrict__ b_dist) {
    int dd = blockIdx.x;        // 0..254 -> d = dd-127
    int c  = threadIdx.x;
    float d  = (float)(dd - 127);
    float e0 = log1pf(fmaxf(d, 0.f));
    float e1 = log1pf(fmaxf(-d, 0.f));
    float e2 = (dd == 127) ? 1.f : 0.f;
    g_table[dd * Cc + c] = e0 * w_dist[c] + e1 * w_dist[Cc + c]
                         + e2 * w_dist[2 * Cc + c] + b_dist[c];
}

// ---------------------------------------------------------------------------
// K0b: convert w_out to tf32 bits
// ---------------------------------------------------------------------------
__global__ void k_wconv(const float* __restrict__ W) {
    int i = blockIdx.x * blockDim.x + threadIdx.x;
    g_Wtf[i] = f2tf(W[i]);
}

// ---------------------------------------------------------------------------
// K1: time_proj = temb @ w_time + b_time (tiny)
// ---------------------------------------------------------------------------
__global__ void k_time_proj(const float* __restrict__ temb,
                            const float* __restrict__ w_time,
                            const float* __restrict__ b_time) {
    int r0 = blockIdx.x * 8;
    int c  = threadIdx.x;
    __shared__ float s[8][TEc];
    for (int i = threadIdx.x; i < 8 * TEc; i += blockDim.x)
        s[i / TEc][i % TEc] = temb[(r0 + i / TEc) * TEc + (i % TEc)];
    __syncthreads();
    float acc[8];
#pragma unroll
    for (int r = 0; r < 8; r++) acc[r] = b_time[c];
    for (int k = 0; k < TEc; k++) {
        float w = w_time[k * Cc + c];
#pragma unroll
        for (int r = 0; r < 8; r++) acc[r] += s[r][k] * w;
    }
#pragma unroll
    for (int r = 0; r < 8; r++) g_time_proj[(r0 + r) * Cc + c] = acc[r];
}

// ---------------------------------------------------------------------------
// K2: act = tf32(silu(time_proj + table[d])) — 2 float4 per thread, 1 pd/8el
// ---------------------------------------------------------------------------
__global__ void k_act(const int* __restrict__ pd) {
    int i   = blockIdx.x * blockDim.x + threadIdx.x;  // over NROW*Cc/8
    int row = i >> 6;
    int c8  = (i & 63) * 2;
    int d   = pd[row];
    int bt  = row >> 7;
    const float4* tpp = (const float4*)g_time_proj + bt * 128 + c8;
    const float4* tbp = (const float4*)g_table + (d + 127) * 128 + c8;
    float4 tp0 = tpp[0], tp1 = tpp[1];
    float4 tb0 = tbp[0], tb1 = tbp[1];
    uint4 v0, v1;
    v0.x = f2tf(silu_fast(tp0.x + tb0.x));
    v0.y = f2tf(silu_fast(tp0.y + tb0.y));
    v0.z = f2tf(silu_fast(tp0.z + tb0.z));
    v0.w = f2tf(silu_fast(tp0.w + tb0.w));
    v1.x = f2tf(silu_fast(tp1.x + tb1.x));
    v1.y = f2tf(silu_fast(tp1.y + tb1.y));
    v1.z = f2tf(silu_fast(tp1.z + tb1.z));
    v1.w = f2tf(silu_fast(tp1.w + tb1.w));
    uint4* dst = (uint4*)g_act + row * 128 + c8;
    dst[0] = v0;
    dst[1] = v1;
}

// ---------------------------------------------------------------------------
// K3: R = act @ w_out + b_out (M=32768,N=512,K=512), tf32 TC,
//     cp.async 3-stage pipeline, ONE sync per k-iter. Writes g_R as tf32.
// ---------------------------------------------------------------------------
#define RG_LDA 36
#define RG_LDB 136
#define RG_AS  (128 * RG_LDA)   // u32 per A stage
#define RG_BS  (32 * RG_LDB)    // u32 per B stage
#define RG_NIT 16               // 512 / 32

__global__ __launch_bounds__(256) void k_rgemm_tc(const float* __restrict__ bias) {
    extern __shared__ unsigned sh[];
    unsigned* As = sh;                 // [3][RG_AS]
    unsigned* Bs = sh + 3 * RG_AS;     // [3][RG_BS]
    unsigned sh_u = (unsigned)__cvta_generic_to_shared(sh);
    unsigned As_u = sh_u;
    unsigned Bs_u = sh_u + 3 * RG_AS * 4;

    int n0 = blockIdx.x * 128;
    int m0 = blockIdx.y * 128;
    int t = threadIdx.x;
    int warp = t >> 5, lane = t & 31;
    int wm = (warp >> 2) * 64, wn = (warp & 3) * 32;
    int grp = lane >> 2, tig = lane & 3;

    float acc[4][4][4];
#pragma unroll
    for (int mi = 0; mi < 4; mi++)
#pragma unroll
        for (int ni = 0; ni < 4; ni++)
#pragma unroll
            for (int q = 0; q < 4; q++) acc[mi][ni][q] = 0.f;

    int am[4], ak[4], bk[4], bn[4];
#pragma unroll
    for (int i = 0; i < 4; i++) {
        int f = t + 256 * i;
        am[i] = f >> 3;  ak[i] = (f & 7) * 4;
        bk[i] = f >> 5;  bn[i] = (f & 31) * 4;
    }

    auto prefetch = [&](int st, int k0) {
#pragma unroll
        for (int i = 0; i < 4; i++) {
            cp16(As_u + (st * RG_AS + am[i] * RG_LDA + ak[i]) * 4,
                 g_act + (size_t)(m0 + am[i]) * Cc + k0 + ak[i]);
            cp16(Bs_u + (st * RG_BS + bk[i] * RG_LDB + bn[i]) * 4,
                 g_Wtf + (size_t)(k0 + bk[i]) * Cc + n0 + bn[i]);
        }
    };

    prefetch(0, 0);  CP_COMMIT();
    prefetch(1, 32); CP_COMMIT();

    for (int it = 0; it < RG_NIT; it++) {
        CP_WAIT(1);
        __syncthreads();   // orders prior-iter MMA reads before this iter's prefetch
        if (it + 2 < RG_NIT) prefetch((it + 2) % 3, (it + 2) * 32);
        CP_COMMIT();

        const unsigned* A = As + (it % 3) * RG_AS;
        const unsigned* B = Bs + (it % 3) * RG_BS;
#pragma unroll
        for (int k8 = 0; k8 < 32; k8 += 8) {
            unsigned a[4][4], b[4][2];
#pragma unroll
            for (int mi = 0; mi < 4; mi++) {
                int r = wm + mi * 16 + grp;
                a[mi][0] = A[r * RG_LDA + k8 + tig];
                a[mi][1] = A[(r + 8) * RG_LDA + k8 + tig];
                a[mi][2] = A[r * RG_LDA + k8 + tig + 4];
                a[mi][3] = A[(r + 8) * RG_LDA + k8 + tig + 4];
            }
#pragma unroll
            for (int ni = 0; ni < 4; ni++) {
                int n = wn + ni * 8 + grp;
                b[ni][0] = B[(k8 + tig) * RG_LDB + n];
                b[ni][1] = B[(k8 + tig + 4) * RG_LDB + n];
            }
#pragma unroll
            for (int mi = 0; mi < 4; mi++)
#pragma unroll
                for (int ni = 0; ni < 4; ni++)
                    mma_tf32(acc[mi][ni], a[mi], b[ni]);
        }
        // no trailing sync: next iter's leading sync provides the ordering
    }

    // epilogue: +bias, convert to tf32 bits for qkgemm
#pragma unroll
    for (int mi = 0; mi < 4; mi++) {
        int r = m0 + wm + mi * 16 + grp;
#pragma unroll
        for (int ni = 0; ni < 4; ni++) {
            int n = n0 + wn + ni * 8 + tig * 2;
            float2 bv = *(const float2*)(bias + n);
            uint2 v0, v1;
            v0.x = f2tf(acc[mi][ni][0] + bv.x); v0.y = f2tf(acc[mi][ni][1] + bv.y);
            v1.x = f2tf(acc[mi][ni][2] + bv.x); v1.y = f2tf(acc[mi][ni][3] + bv.y);
            *(uint2*)(g_R + (size_t)r * Cc + n) = v0;
            *(uint2*)(g_R + (size_t)(r + 8) * Cc + n) = v1;
        }
    }
}

// ---------------------------------------------------------------------------
// K4: out[b,d,h,t,s] = sum_f qk[..f] * R[..f]
//     One block per (b,h,t): M=256 (all d), N=128 (s), K=64. 512 threads,
//     16 warps in 4x4 grid (warp tile 64x32). R tile read exactly once.
// ---------------------------------------------------------------------------
#define QG_LD   68
#define QG_SZA  (256 * QG_LD)
#define QG_SZB  (128 * QG_LD)
__global__ __launch_bounds__(512) void k_qkgemm_tc(const float* __restrict__ qk,
                                                   float* __restrict__ out) {
    extern __shared__ unsigned sh[];
    unsigned* As = sh;             // [256][68]  (d x f)
    unsigned* Bs = sh + QG_SZA;    // [128][68]  (s x f)
    unsigned Bs_u = (unsigned)__cvta_generic_to_shared(Bs);

    int batch = blockIdx.x;           // b*H*T + h*T + t
    int b = batch >> 10;
    int h = (batch >> 7) & 7;
    int tt = batch & 127;

    size_t baseA = (((size_t)b * Dd * Hh + h) * Tt + tt) * Ff;        // d=0
    size_t baseB = (((size_t)b * Tt + tt) * Ss) * Cc + (size_t)h * Ff;
    size_t baseO = (((size_t)b * Dd * Hh + h) * Tt + tt) * Ss;        // d=0
    const size_t strideA = (size_t)Hh * Tt * Ff;   // 65536
    const size_t strideO = (size_t)Hh * Tt * Ss;   // 131072

    int t = threadIdx.x;
    int warp = t >> 5, lane = t & 31;
    int wm = (warp >> 2) * 64, wn = (warp & 3) * 32;
    int grp = lane >> 2, tig = lane & 3;

    // B tile async: 128 rows x 64 f = 2048 float4 -> 4 per thread
#pragma unroll
    for (int i = 0; i < 4; i++) {
        int f = t + 512 * i;
        int m = f >> 4, kp = (f & 15) * 4;
        cp16(Bs_u + (m * QG_LD + kp) * 4, g_R + baseB + (size_t)m * Cc + kp);
    }
    CP_COMMIT();

    float acc[4][4][4];
#pragma unroll
    for (int mi = 0; mi < 4; mi++)
#pragma unroll
        for (int ni = 0; ni < 4; ni++)
#pragma unroll
            for (int q = 0; q < 4; q++) acc[mi][ni][q] = 0.f;

    // A tile: 256 rows x 64 f = 4096 float4 -> 8 per thread (LDG+cvt+STS)
#pragma unroll
    for (int i = 0; i < 8; i++) {
        int f = t + 512 * i;
        int m = f >> 4, kp = (f & 15) * 4;
        float4 v = *(const float4*)(qk + baseA + (size_t)m * strideA + kp);
        unsigned* dst = &As[m * QG_LD + kp];
        dst[0] = f2tf(v.x); dst[1] = f2tf(v.y);
        dst[2] = f2tf(v.z); dst[3] = f2tf(v.w);
    }

    CP_WAIT(0);
    __syncthreads();

#pragma unroll
    for (int k8 = 0; k8 < 64; k8 += 8) {
        unsigned a[4][4], b2[4][2];
#pragma unroll
        for (int mi = 0; mi < 4; mi++) {
            int r = wm + mi * 16 + grp;
            a[mi][0] = As[r * QG_LD + k8 + tig];
            a[mi][1] = As[(r + 8) * QG_LD + k8 + tig];
            a[mi][2] = As[r * QG_LD + k8 + tig + 4];
            a[mi][3] = As[(r + 8) * QG_LD + k8 + tig + 4];
        }
#pragma unroll
        for (int ni = 0; ni < 4; ni++) {
            int n = wn + ni * 8 + grp;
            b2[ni][0] = Bs[n * QG_LD + k8 + tig];
            b2[ni][1] = Bs[n * QG_LD + k8 + tig + 4];
        }
#pragma unroll
        for (int mi = 0; mi < 4; mi++)
#pragma unroll
            for (int ni = 0; ni < 4; ni++)
                mma_tf32(acc[mi][ni], a[mi], b2[ni]);
    }

#pragma unroll
    for (int mi = 0; mi < 4; mi++) {
        int r = wm + mi * 16 + grp;
#pragma unroll
        for (int ni = 0; ni < 4; ni++) {
            int n = wn + ni * 8 + tig * 2;
            float2 v0, v1;
            v0.x = acc[mi][ni][0]; v0.y = acc[mi][ni][1];
            v1.x = acc[mi][ni][2]; v1.y = acc[mi][ni][3];
            *(float2*)(out + baseO + (size_t)r * strideO + n) = v0;
            *(float2*)(out + baseO + (size_t)(r + 8) * strideO + n) = v1;
        }
    }
}

// ---------------------------------------------------------------------------
extern "C" void kernel_launch(void* const* d_in, const int* in_sizes, int n_in,
                              void* d_out, int out_size) {
    const float* qk     = (const float*)d_in[0];
    const float* temb   = (const float*)d_in[1];
    const int*   pd     = (const int*)d_in[2];
    const float* w_dist = (const float*)d_in[3];
    const float* b_dist = (const float*)d_in[4];
    const float* w_time = (const float*)d_in[5];
    const float* b_time = (const float*)d_in[6];
    const float* w_out  = (const float*)d_in[7];
    const float* b_out  = (const float*)d_in[8];
    float* out = (float*)d_out;

    const int rg_smem = 3 * (RG_AS + RG_BS) * 4;      // 107,520 B (2 blk/SM)
    const int qg_smem = (QG_SZA + QG_SZB) * 4;        // 104,448 B
    cudaFuncSetAttribute(k_rgemm_tc, cudaFuncAttributeMaxDynamicSharedMemorySize, rg_smem);
    cudaFuncSetAttribute(k_qkgemm_tc, cudaFuncAttributeMaxDynamicSharedMemorySize, qg_smem);

    k_table<<<255, 512>>>(w_dist, b_dist);
    k_wconv<<<Cc * Cc / 512, 512>>>(w_out);
    k_time_proj<<<BT / 8, 512>>>(temb, w_time, b_time);
    k_act<<<(NROW * Cc / 8) / 256, 256>>>(pd);
    k_rgemm_tc<<<dim3(Cc / 128, NROW / 128), 256, rg_smem>>>(b_out);
    k_qkgemm_tc<<<Bb * Hh * Tt, 512, qg_smem>>>(qk, out);
}

// round 8
// speedup vs baseline: 1.1020x; 1.1020x over previous
#include <cuda_runtime.h>
#include <math.h>

// Problem constants
#define Bb 2
#define Dd 256
#define Hh 8
#define Tt 128
#define Ff 64
#define Cc 512
#define TEc 512
#define Ss 128
#define NROW (Bb * Tt * Ss)   // 32768
#define BT (Bb * Tt)          // 256

// Scratch (no cudaMalloc allowed)
__device__ float    g_time_proj[BT * Cc];
__device__ float    g_table[256 * Cc];
__device__ unsigned g_act[NROW * Cc];   // tf32 bits
__device__ unsigned g_R[NROW * Cc];     // tf32 bits
__device__ unsigned g_Wtf[Cc * Cc];     // w_out as tf32 bits

// ---------------------------------------------------------------------------
// helpers
// ---------------------------------------------------------------------------
__device__ __forceinline__ unsigned f2tf(float x) {
    unsigned r;
    asm("cvt.rna.tf32.f32 %0, %1;" : "=r"(r) : "f"(x));
    return r;
}
__device__ __forceinline__ float tanh_fast(float x) {
    float y;
    asm("tanh.approx.f32 %0, %1;" : "=f"(y) : "f"(x));
    return y;
}
__device__ __forceinline__ float silu_fast(float x) {
    return x * (0.5f * tanh_fast(0.5f * x) + 0.5f);
}
__device__ __forceinline__ void mma_tf32(float* c, const unsigned* a, const unsigned* b) {
    asm volatile(
        "mma.sync.aligned.m16n8k8.row.col.f32.tf32.tf32.f32 "
        "{%0,%1,%2,%3}, {%4,%5,%6,%7}, {%8,%9}, {%0,%1,%2,%3};"
        : "+f"(c[0]), "+f"(c[1]), "+f"(c[2]), "+f"(c[3])
        : "r"(a[0]), "r"(a[1]), "r"(a[2]), "r"(a[3]),
          "r"(b[0]), "r"(b[1]));
}
__device__ __forceinline__ void cp16(unsigned sdst, const void* gsrc) {
    asm volatile("cp.async.cg.shared.global [%0], [%1], 16;\n"
                 :: "r"(sdst), "l"(gsrc));
}
#define CP_COMMIT() asm volatile("cp.async.commit_group;\n" ::: "memory")
#define CP_WAIT(n)  asm volatile("cp.async.wait_group %0;\n" :: "n"(n) : "memory")

// ---------------------------------------------------------------------------
// K0 (fused prep): blocks 0..254 -> distance table
//                  blocks 255..766 -> w_out tf32 convert
//                  blocks 767..798 -> time_proj GEMV
// ---------------------------------------------------------------------------
__global__ __launch_bounds__(512) void k_prep(const float* __restrict__ w_dist,
                                              const float* __restrict__ b_dist,
                                              const float* __restrict__ W,
                                              const float* __restrict__ temb,
                                              const float* __restrict__ w_time,
                                              const float* __restrict__ b_time) {
    int blk = blockIdx.x;
    if (blk < 255) {
        // distance table (includes b_dist)
        int dd = blk;               // d = dd-127
        int c  = threadIdx.x;
        float d  = (float)(dd - 127);
        float e0 = log1pf(fmaxf(d, 0.f));
        float e1 = log1pf(fmaxf(-d, 0.f));
        float e2 = (dd == 127) ? 1.f : 0.f;
        g_table[dd * Cc + c] = e0 * w_dist[c] + e1 * w_dist[Cc + c]
                             + e2 * w_dist[2 * Cc + c] + b_dist[c];
    } else if (blk < 767) {
        int i = (blk - 255) * 512 + threadIdx.x;
        g_Wtf[i] = f2tf(W[i]);
    } else {
        // time_proj: 8 rows per block
        int r0 = (blk - 767) * 8;
        int c  = threadIdx.x;
        __shared__ float s[8][TEc];
        for (int i = threadIdx.x; i < 8 * TEc; i += blockDim.x)
            s[i / TEc][i % TEc] = temb[(r0 + i / TEc) * TEc + (i % TEc)];
        __syncthreads();
        float acc[8];
#pragma unroll
        for (int r = 0; r < 8; r++) acc[r] = b_time[c];
        for (int k = 0; k < TEc; k++) {
            float w = w_time[k * Cc + c];
#pragma unroll
            for (int r = 0; r < 8; r++) acc[r] += s[r][k] * w;
        }
#pragma unroll
        for (int r = 0; r < 8; r++) g_time_proj[(r0 + r) * Cc + c] = acc[r];
    }
}

// ---------------------------------------------------------------------------
// K2: act = tf32(silu(time_proj + table[d])) — 2 float4 per thread, 1 pd/8el
// ---------------------------------------------------------------------------
__global__ void k_act(const int* __restrict__ pd) {
    int i   = blockIdx.x * blockDim.x + threadIdx.x;  // over NROW*Cc/8
    int row = i >> 6;
    int c8  = (i & 63) * 2;
    int d   = pd[row];
    int bt  = row >> 7;
    const float4* tpp = (const float4*)g_time_proj + bt * 128 + c8;
    const float4* tbp = (const float4*)g_table + (d + 127) * 128 + c8;
    float4 tp0 = tpp[0], tp1 = tpp[1];
    float4 tb0 = tbp[0], tb1 = tbp[1];
    uint4 v0, v1;
    v0.x = f2tf(silu_fast(tp0.x + tb0.x));
    v0.y = f2tf(silu_fast(tp0.y + tb0.y));
    v0.z = f2tf(silu_fast(tp0.z + tb0.z));
    v0.w = f2tf(silu_fast(tp0.w + tb0.w));
    v1.x = f2tf(silu_fast(tp1.x + tb1.x));
    v1.y = f2tf(silu_fast(tp1.y + tb1.y));
    v1.z = f2tf(silu_fast(tp1.z + tb1.z));
    v1.w = f2tf(silu_fast(tp1.w + tb1.w));
    uint4* dst = (uint4*)g_act + row * 128 + c8;
    dst[0] = v0;
    dst[1] = v1;
}

// ---------------------------------------------------------------------------
// K3: R = act @ w_out + b_out (M=32768,N=512,K=512), tf32 TC,
//     cp.async 3-stage pipeline, ONE sync per k-iter. Writes g_R as tf32.
// ---------------------------------------------------------------------------
#define RG_LDA 36
#define RG_LDB 136
#define RG_AS  (128 * RG_LDA)   // u32 per A stage
#define RG_BS  (32 * RG_LDB)    // u32 per B stage
#define RG_NIT 16               // 512 / 32

__global__ __launch_bounds__(256) void k_rgemm_tc(const float* __restrict__ bias) {
    extern __shared__ unsigned sh[];
    unsigned* As = sh;                 // [3][RG_AS]
    unsigned* Bs = sh + 3 * RG_AS;     // [3][RG_BS]
    unsigned sh_u = (unsigned)__cvta_generic_to_shared(sh);
    unsigned As_u = sh_u;
    unsigned Bs_u = sh_u + 3 * RG_AS * 4;

    int n0 = blockIdx.x * 128;
    int m0 = blockIdx.y * 128;
    int t = threadIdx.x;
    int warp = t >> 5, lane = t & 31;
    int wm = (warp >> 2) * 64, wn = (warp & 3) * 32;
    int grp = lane >> 2, tig = lane & 3;

    float acc[4][4][4];
#pragma unroll
    for (int mi = 0; mi < 4; mi++)
#pragma unroll
        for (int ni = 0; ni < 4; ni++)
#pragma unroll
            for (int q = 0; q < 4; q++) acc[mi][ni][q] = 0.f;

    int am[4], ak[4], bk[4], bn[4];
#pragma unroll
    for (int i = 0; i < 4; i++) {
        int f = t + 256 * i;
        am[i] = f >> 3;  ak[i] = (f & 7) * 4;
        bk[i] = f >> 5;  bn[i] = (f & 31) * 4;
    }

    auto prefetch = [&](int st, int k0) {
#pragma unroll
        for (int i = 0; i < 4; i++) {
            cp16(As_u + (st * RG_AS + am[i] * RG_LDA + ak[i]) * 4,
                 g_act + (size_t)(m0 + am[i]) * Cc + k0 + ak[i]);
            cp16(Bs_u + (st * RG_BS + bk[i] * RG_LDB + bn[i]) * 4,
                 g_Wtf + (size_t)(k0 + bk[i]) * Cc + n0 + bn[i]);
        }
    };

    prefetch(0, 0);  CP_COMMIT();
    prefetch(1, 32); CP_COMMIT();

    for (int it = 0; it < RG_NIT; it++) {
        CP_WAIT(1);
        __syncthreads();   // orders prior-iter MMA reads before this iter's prefetch
        if (it + 2 < RG_NIT) prefetch((it + 2) % 3, (it + 2) * 32);
        CP_COMMIT();

        const unsigned* A = As + (it % 3) * RG_AS;
        const unsigned* B = Bs + (it % 3) * RG_BS;
#pragma unroll
        for (int k8 = 0; k8 < 32; k8 += 8) {
            unsigned a[4][4], b[4][2];
#pragma unroll
            for (int mi = 0; mi < 4; mi++) {
                int r = wm + mi * 16 + grp;
                a[mi][0] = A[r * RG_LDA + k8 + tig];
                a[mi][1] = A[(r + 8) * RG_LDA + k8 + tig];
                a[mi][2] = A[r * RG_LDA + k8 + tig + 4];
                a[mi][3] = A[(r + 8) * RG_LDA + k8 + tig + 4];
            }
#pragma unroll
            for (int ni = 0; ni < 4; ni++) {
                int n = wn + ni * 8 + grp;
                b[ni][0] = B[(k8 + tig) * RG_LDB + n];
                b[ni][1] = B[(k8 + tig + 4) * RG_LDB + n];
            }
#pragma unroll
            for (int mi = 0; mi < 4; mi++)
#pragma unroll
                for (int ni = 0; ni < 4; ni++)
                    mma_tf32(acc[mi][ni], a[mi], b[ni]);
        }
        // no trailing sync: next iter's leading sync provides the ordering
    }

    // epilogue: +bias, convert to tf32 bits for qkgemm
#pragma unroll
    for (int mi = 0; mi < 4; mi++) {
        int r = m0 + wm + mi * 16 + grp;
#pragma unroll
        for (int ni = 0; ni < 4; ni++) {
            int n = n0 + wn + ni * 8 + tig * 2;
            float2 bv = *(const float2*)(bias + n);
            uint2 v0, v1;
            v0.x = f2tf(acc[mi][ni][0] + bv.x); v0.y = f2tf(acc[mi][ni][1] + bv.y);
            v1.x = f2tf(acc[mi][ni][2] + bv.x); v1.y = f2tf(acc[mi][ni][3] + bv.y);
            *(uint2*)(g_R + (size_t)r * Cc + n) = v0;
            *(uint2*)(g_R + (size_t)(r + 8) * Cc + n) = v1;
        }
    }
}

// ---------------------------------------------------------------------------
// K4: out[b,d,h,t,s] = sum_f qk[..f] * R[..f]  — M=128 per block, 256 thr,
//     whole K=64 staged once; B via cp.async from tf32 g_R, A via LDG+cvt.
//     69.6 KB smem -> 2+ blocks/SM (load/epilogue phases overlap across blocks)
// ---------------------------------------------------------------------------
#define QG_LD  68
#define QG_SZ  (128 * QG_LD)
__global__ __launch_bounds__(256) void k_qkgemm_tc(const float* __restrict__ qk,
                                                   float* __restrict__ out) {
    extern __shared__ unsigned sh[];
    unsigned* As = sh;            // [128][68]  (d x f)
    unsigned* Bs = sh + QG_SZ;    // [128][68]  (s x f)
    unsigned Bs_u = (unsigned)__cvta_generic_to_shared(Bs);

    int bid = blockIdx.x;
    int dblk = bid & 1;
    int batch = bid >> 1;             // b*H*T + h*T + t
    int b = batch >> 10;
    int h = (batch >> 7) & 7;
    int tt = batch & 127;
    int d0 = dblk * 128;

    size_t baseA = ((((size_t)b * Dd + d0) * Hh + h) * Tt + tt) * Ff;
    size_t baseB = (((size_t)b * Tt + tt) * Ss) * Cc + (size_t)h * Ff;
    size_t baseO = ((((size_t)b * Dd + d0) * Hh + h) * Tt + tt) * Ss;
    const size_t strideA = (size_t)Hh * Tt * Ff;   // 65536
    const size_t strideO = (size_t)Hh * Tt * Ss;   // 131072

    int t = threadIdx.x;
    int warp = t >> 5, lane = t & 31;
    int wm = (warp >> 2) * 64, wn = (warp & 3) * 32;
    int grp = lane >> 2, tig = lane & 3;

    // B tile async (128 rows x 64 f = 8 x 16B per thread)
#pragma unroll
    for (int i = 0; i < 8; i++) {
        int f = t + 256 * i;
        int m = f >> 4, kp = (f & 15) * 4;
        cp16(Bs_u + (m * QG_LD + kp) * 4, g_R + baseB + (size_t)m * Cc + kp);
    }
    CP_COMMIT();

    float acc[4][4][4];
#pragma unroll
    for (int mi = 0; mi < 4; mi++)
#pragma unroll
        for (int ni = 0; ni < 4; ni++)
#pragma unroll
            for (int q = 0; q < 4; q++) acc[mi][ni][q] = 0.f;

    // A tile: LDG float4 + cvt + STS (overlaps with B cp.async)
#pragma unroll
    for (int i = 0; i < 8; i++) {
        int f = t + 256 * i;
        int m = f >> 4, kp = (f & 15) * 4;
        float4 v = *(const float4*)(qk + baseA + (size_t)m * strideA + kp);
        unsigned* dst = &As[m * QG_LD + kp];
        dst[0] = f2tf(v.x); dst[1] = f2tf(v.y);
        dst[2] = f2tf(v.z); dst[3] = f2tf(v.w);
    }

    CP_WAIT(0);
    __syncthreads();

#pragma unroll
    for (int k8 = 0; k8 < 64; k8 += 8) {
        unsigned a[4][4], b2[4][2];
#pragma unroll
        for (int mi = 0; mi < 4; mi++) {
            int r = wm + mi * 16 + grp;
            a[mi][0] = As[r * QG_LD + k8 + tig];
            a[mi][1] = As[(r + 8) * QG_LD + k8 + tig];
            a[mi][2] = As[r * QG_LD + k8 + tig + 4];
            a[mi][3] = As[(r + 8) * QG_LD + k8 + tig + 4];
        }
#pragma unroll
        for (int ni = 0; ni < 4; ni++) {
            int n = wn + ni * 8 + grp;
            b2[ni][0] = Bs[n * QG_LD + k8 + tig];
            b2[ni][1] = Bs[n * QG_LD + k8 + tig + 4];
        }
#pragma unroll
        for (int mi = 0; mi < 4; mi++)
#pragma unroll
            for (int ni = 0; ni < 4; ni++)
                mma_tf32(acc[mi][ni], a[mi], b2[ni]);
    }

#pragma unroll
    for (int mi = 0; mi < 4; mi++) {
        int r = wm + mi * 16 + grp;
#pragma unroll
        for (int ni = 0; ni < 4; ni++) {
            int n = wn + ni * 8 + tig * 2;
            float2 v0, v1;
            v0.x = acc[mi][ni][0]; v0.y = acc[mi][ni][1];
            v1.x = acc[mi][ni][2]; v1.y = acc[mi][ni][3];
            *(float2*)(out + baseO + (size_t)r * strideO + n) = v0;
            *(float2*)(out + baseO + (size_t)(r + 8) * strideO + n) = v1;
        }
    }
}

// ---------------------------------------------------------------------------
extern "C" void kernel_launch(void* const* d_in, const int* in_sizes, int n_in,
                              void* d_out, int out_size) {
    const float* qk     = (const float*)d_in[0];
    const float* temb   = (const float*)d_in[1];
    const int*   pd     = (const int*)d_in[2];
    const float* w_dist = (const float*)d_in[3];
    const float* b_dist = (const float*)d_in[4];
    const float* w_time = (const float*)d_in[5];
    const float* b_time = (const float*)d_in[6];
    const float* w_out  = (const float*)d_in[7];
    const float* b_out  = (const float*)d_in[8];
    float* out = (float*)d_out;

    const int rg_smem = 3 * (RG_AS + RG_BS) * 4;   // 107,520 B (2 blk/SM)
    const int qg_smem = 2 * QG_SZ * 4;             //  69,632 B (2+ blk/SM)
    cudaFuncSetAttribute(k_rgemm_tc, cudaFuncAttributeMaxDynamicSharedMemorySize, rg_smem);
    cudaFuncSetAttribute(k_qkgemm_tc, cudaFuncAttributeMaxDynamicSharedMemorySize, qg_smem);

    k_prep<<<799, 512>>>(w_dist, b_dist, w_out, temb, w_time, b_time);
    k_act<<<(NROW * Cc / 8) / 256, 256>>>(pd);
    k_rgemm_tc<<<dim3(Cc / 128, NROW / 128), 256, rg_smem>>>(b_out);
    k_qkgemm_tc<<<Bb * Hh * Tt * 2, 256, qg_smem>>>(qk, out);
}

// round 9
// speedup vs baseline: 1.1191x; 1.0155x over previous
#include <cuda_runtime.h>
#include <math.h>

// Problem constants
#define Bb 2
#define Dd 256
#define Hh 8
#define Tt 128
#define Ff 64
#define Cc 512
#define TEc 512
#define Ss 128
#define NROW (Bb * Tt * Ss)   // 32768
#define BT (Bb * Tt)          // 256

// Scratch (no cudaMalloc allowed)
__device__ float    g_time_proj[BT * Cc];
__device__ float    g_table[256 * Cc];
// g_act in MMA-fragment layout:
//   u32 addr = ((m16*64 + k8)*32 + lane)*4 + reg
//   lane = (m%8)*4 + (k%4), reg = ((m%16)/8) + 2*((k%8)/4)
__device__ unsigned g_act[NROW * Cc];
__device__ unsigned g_R[NROW * Cc];     // tf32 bits, row-major (qkgemm B)
// g_Wtf in B-pair layout: u32 addr = (k/8)*4096 + n*8 + (k%4)*2 + ((k/4)%2)
__device__ unsigned g_Wtf[Cc * Cc];

// ---------------------------------------------------------------------------
// helpers
// ---------------------------------------------------------------------------
__device__ __forceinline__ unsigned f2tf(float x) {
    unsigned r;
    asm("cvt.rna.tf32.f32 %0, %1;" : "=r"(r) : "f"(x));
    return r;
}
__device__ __forceinline__ float tanh_fast(float x) {
    float y;
    asm("tanh.approx.f32 %0, %1;" : "=f"(y) : "f"(x));
    return y;
}
__device__ __forceinline__ float silu_fast(float x) {
    return x * (0.5f * tanh_fast(0.5f * x) + 0.5f);
}
__device__ __forceinline__ void mma_tf32(float* c, const unsigned* a, const unsigned* b) {
    asm volatile(
        "mma.sync.aligned.m16n8k8.row.col.f32.tf32.tf32.f32 "
        "{%0,%1,%2,%3}, {%4,%5,%6,%7}, {%8,%9}, {%0,%1,%2,%3};"
        : "+f"(c[0]), "+f"(c[1]), "+f"(c[2]), "+f"(c[3])
        : "r"(a[0]), "r"(a[1]), "r"(a[2]), "r"(a[3]),
          "r"(b[0]), "r"(b[1]));
}
__device__ __forceinline__ void cp16(unsigned sdst, const void* gsrc) {
    asm volatile("cp.async.cg.shared.global [%0], [%1], 16;\n"
                 :: "r"(sdst), "l"(gsrc));
}
#define CP_COMMIT() asm volatile("cp.async.commit_group;\n" ::: "memory")
#define CP_WAIT(n)  asm volatile("cp.async.wait_group %0;\n" :: "n"(n) : "memory")

// ---------------------------------------------------------------------------
// K0 (fused prep): blocks 0..254   -> distance table
//                  blocks 255..318 -> w_out pair-layout tf32 convert
//                  blocks 319..350 -> time_proj GEMV
// ---------------------------------------------------------------------------
__global__ __launch_bounds__(512) void k_prep(const float* __restrict__ w_dist,
                                              const float* __restrict__ b_dist,
                                              const float* __restrict__ W,
                                              const float* __restrict__ temb,
                                              const float* __restrict__ w_time,
                                              const float* __restrict__ b_time) {
    int blk = blockIdx.x;
    if (blk < 255) {
        int dd = blk;               // d = dd-127
        int c  = threadIdx.x;
        float d  = (float)(dd - 127);
        float e0 = log1pf(fmaxf(d, 0.f));
        float e1 = log1pf(fmaxf(-d, 0.f));
        float e2 = (dd == 127) ? 1.f : 0.f;
        g_table[dd * Cc + c] = e0 * w_dist[c] + e1 * w_dist[Cc + c]
                             + e2 * w_dist[2 * Cc + c] + b_dist[c];
    } else if (blk < 319) {
        // pair-layout W convert: thread handles one (k8, n): 8 k-values
        int j  = (blk - 255) * 512 + threadIdx.x;   // 0..32767
        int n  = j & 511;
        int k8 = j >> 9;                             // 0..63
        unsigned s[8];
#pragma unroll
        for (int q = 0; q < 8; q++)
            s[(q & 3) * 2 + (q >> 2)] = f2tf(W[(size_t)(k8 * 8 + q) * Cc + n]);
        uint4* dst = (uint4*)(g_Wtf + (size_t)k8 * 4096 + n * 8);
        dst[0] = make_uint4(s[0], s[1], s[2], s[3]);
        dst[1] = make_uint4(s[4], s[5], s[6], s[7]);
    } else {
        int r0 = (blk - 319) * 8;
        int c  = threadIdx.x;
        __shared__ float s[8][TEc];
        for (int i = threadIdx.x; i < 8 * TEc; i += blockDim.x)
            s[i / TEc][i % TEc] = temb[(r0 + i / TEc) * TEc + (i % TEc)];
        __syncthreads();
        float acc[8];
#pragma unroll
        for (int r = 0; r < 8; r++) acc[r] = b_time[c];
        for (int k = 0; k < TEc; k++) {
            float w = w_time[k * Cc + c];
#pragma unroll
            for (int r = 0; r < 8; r++) acc[r] += s[r][k] * w;
        }
#pragma unroll
        for (int r = 0; r < 8; r++) g_time_proj[(r0 + r) * Cc + c] = acc[r];
    }
}

// ---------------------------------------------------------------------------
// K2: act -> fragment layout. Block = one m16 (16 rows, one bt) x 8 k8-chunks.
//     Table rows + tp staged in smem; each thread emits one uint4 fragment.
// ---------------------------------------------------------------------------
__global__ __launch_bounds__(256) void k_act(const int* __restrict__ pd) {
    __shared__ float s_tp[64];
    __shared__ float s_tb[16][68];
    int m16   = blockIdx.x >> 3;          // 0..2047
    int k8b   = (blockIdx.x & 7) * 8;     // k8 chunk base (0..56)
    int kbase = k8b * 8;                  // 64 k values
    int bt    = m16 >> 3;
    int t = threadIdx.x;
    if (t < 64) s_tp[t] = g_time_proj[bt * Cc + kbase + t];
#pragma unroll
    for (int i = 0; i < 4; i++) {
        int f = t + 256 * i;              // 0..1023
        int r = f >> 6, c = f & 63;
        int d = pd[m16 * 16 + r];
        s_tb[r][c] = g_table[(d + 127) * Cc + kbase + c];
    }
    __syncthreads();
    int kk8 = t >> 5, lane = t & 31;
    int grp = lane >> 2, tig = lane & 3;
    int k1 = kk8 * 8 + tig, k2 = k1 + 4;
    float tp1 = s_tp[k1], tp2 = s_tp[k2];
    uint4 v;
    v.x = f2tf(silu_fast(tp1 + s_tb[grp][k1]));        // (m,   k)
    v.y = f2tf(silu_fast(tp1 + s_tb[grp + 8][k1]));    // (m+8, k)
    v.z = f2tf(silu_fast(tp2 + s_tb[grp][k2]));        // (m,   k+4)
    v.w = f2tf(silu_fast(tp2 + s_tb[grp + 8][k2]));    // (m+8, k+4)
    ((uint4*)g_act)[(m16 * 64 + k8b + kk8) * 32 + lane] = v;
}

// ---------------------------------------------------------------------------
// K3: R = act @ w_out + b_out (M=32768,N=512,K=512), tf32 TC
//     Fragment-layout operands: A = 1 LDS.128/mi, B = 1 LDS.64/ni.
//     cp.async 3-stage, one sync per k-iter. Writes g_R row-major tf32.
// ---------------------------------------------------------------------------
#define RG_AS  4096    // u32 per A stage (128x32 fragment-packed)
#define RG_BS  4096    // u32 per B stage (32x128 pair-packed)
#define RG_NIT 16      // 512 / 32

__global__ __launch_bounds__(256) void k_rgemm_tc(const float* __restrict__ bias) {
    extern __shared__ unsigned sh[];
    unsigned* As = sh;                 // [3][RG_AS]
    unsigned* Bs = sh + 3 * RG_AS;     // [3][RG_BS]
    unsigned sh_u = (unsigned)__cvta_generic_to_shared(sh);
    unsigned As_u = sh_u;
    unsigned Bs_u = sh_u + 3 * RG_AS * 4;

    int n0 = blockIdx.x * 128;
    int m0 = blockIdx.y * 128;
    int M0 = m0 >> 4;                  // m16 tile base
    int t = threadIdx.x;
    int warp = t >> 5, lane = t & 31;
    int wm = (warp >> 2) * 64, wn = (warp & 3) * 32;
    int grp = lane >> 2, tig = lane & 3;

    float acc[4][4][4];
#pragma unroll
    for (int mi = 0; mi < 4; mi++)
#pragma unroll
        for (int ni = 0; ni < 4; ni++)
#pragma unroll
            for (int q = 0; q < 4; q++) acc[mi][ni][q] = 0.f;

    auto prefetch = [&](int st, int K0g) {   // K0g = k0/8
#pragma unroll
        for (int i = 0; i < 4; i++) {
            int idx = t + 256 * i;           // 0..1023 (16B units)
            // A: chunk (M0 + idx>>7, K0g + (idx>>5)&3), lane idx&31
            cp16(As_u + (st * RG_AS + idx * 4) * 4,
                 g_act + (size_t)(M0 + (idx >> 7)) * 8192
                       + (size_t)(K0g + ((idx >> 5) & 3)) * 128 + (idx & 31) * 4);
            // B: chunk K0g + idx>>8, n-slice offset
            cp16(Bs_u + (st * RG_BS + idx * 4) * 4,
                 g_Wtf + (size_t)(K0g + (idx >> 8)) * 4096
                       + (size_t)n0 * 8 + (idx & 255) * 4);
        }
    };

    prefetch(0, 0);  CP_COMMIT();
    prefetch(1, 4);  CP_COMMIT();

    int mt = wm >> 4;   // warp m16 base within tile (0 or 4)

    for (int it = 0; it < RG_NIT; it++) {
        CP_WAIT(1);
        __syncthreads();
        if (it + 2 < RG_NIT) prefetch((it + 2) % 3, (it + 2) * 4);
        CP_COMMIT();

        const uint4* A4 = (const uint4*)(As + (it % 3) * RG_AS);
        const uint2* B2 = (const uint2*)(Bs + (it % 3) * RG_BS);
#pragma unroll
        for (int kk8 = 0; kk8 < 4; kk8++) {
            uint4 a[4];
            uint2 b[4];
#pragma unroll
            for (int mi = 0; mi < 4; mi++)
                a[mi] = A4[((mt + mi) * 4 + kk8) * 32 + lane];
#pragma unroll
            for (int ni = 0; ni < 4; ni++)
                b[ni] = B2[kk8 * 512 + (wn + ni * 8 + grp) * 4 + tig];
#pragma unroll
            for (int mi = 0; mi < 4; mi++)
#pragma unroll
                for (int ni = 0; ni < 4; ni++)
                    mma_tf32(acc[mi][ni], (const unsigned*)&a[mi],
                             (const unsigned*)&b[ni]);
        }
        // no trailing sync: next iter's leading sync provides the ordering
    }

    // epilogue: +bias, convert to tf32 bits for qkgemm (row-major g_R)
#pragma unroll
    for (int mi = 0; mi < 4; mi++) {
        int r = m0 + wm + mi * 16 + grp;
#pragma unroll
        for (int ni = 0; ni < 4; ni++) {
            int n = n0 + wn + ni * 8 + tig * 2;
            float2 bv = *(const float2*)(bias + n);
            uint2 v0, v1;
            v0.x = f2tf(acc[mi][ni][0] + bv.x); v0.y = f2tf(acc[mi][ni][1] + bv.y);
            v1.x = f2tf(acc[mi][ni][2] + bv.x); v1.y = f2tf(acc[mi][ni][3] + bv.y);
            *(uint2*)(g_R + (size_t)r * Cc + n) = v0;
            *(uint2*)(g_R + (size_t)(r + 8) * Cc + n) = v1;
        }
    }
}

// ---------------------------------------------------------------------------
// K4: out[b,d,h,t,s] = sum_f qk[..f] * R[..f]  — M=128 per block, 256 thr,
//     whole K=64 staged once; B via cp.async from tf32 g_R, A via LDG+cvt.
//     (DRAM-bound at ~its traffic floor — unchanged from round 8)
// ---------------------------------------------------------------------------
#define QG_LD  68
#define QG_SZ  (128 * QG_LD)
__global__ __launch_bounds__(256) void k_qkgemm_tc(const float* __restrict__ qk,
                                                   float* __restrict__ out) {
    extern __shared__ unsigned sh[];
    unsigned* As = sh;            // [128][68]  (d x f)
    unsigned* Bs = sh + QG_SZ;    // [128][68]  (s x f)
    unsigned Bs_u = (unsigned)__cvta_generic_to_shared(Bs);

    int bid = blockIdx.x;
    int dblk = bid & 1;
    int batch = bid >> 1;             // b*H*T + h*T + t
    int b = batch >> 10;
    int h = (batch >> 7) & 7;
    int tt = batch & 127;
    int d0 = dblk * 128;

    size_t baseA = ((((size_t)b * Dd + d0) * Hh + h) * Tt + tt) * Ff;
    size_t baseB = (((size_t)b * Tt + tt) * Ss) * Cc + (size_t)h * Ff;
    size_t baseO = ((((size_t)b * Dd + d0) * Hh + h) * Tt + tt) * Ss;
    const size_t strideA = (size_t)Hh * Tt * Ff;   // 65536
    const size_t strideO = (size_t)Hh * Tt * Ss;   // 131072

    int t = threadIdx.x;
    int warp = t >> 5, lane = t & 31;
    int wm = (warp >> 2) * 64, wn = (warp & 3) * 32;
    int grp = lane >> 2, tig = lane & 3;

    // B tile async (128 rows x 64 f = 8 x 16B per thread)
#pragma unroll
    for (int i = 0; i < 8; i++) {
        int f = t + 256 * i;
        int m = f >> 4, kp = (f & 15) * 4;
        cp16(Bs_u + (m * QG_LD + kp) * 4, g_R + baseB + (size_t)m * Cc + kp);
    }
    CP_COMMIT();

    float acc[4][4][4];
#pragma unroll
    for (int mi = 0; mi < 4; mi++)
#pragma unroll
        for (int ni = 0; ni < 4; ni++)
#pragma unroll
            for (int q = 0; q < 4; q++) acc[mi][ni][q] = 0.f;

    // A tile: LDG float4 + cvt + STS (overlaps with B cp.async)
#pragma unroll
    for (int i = 0; i < 8; i++) {
        int f = t + 256 * i;
        int m = f >> 4, kp = (f & 15) * 4;
        float4 v = *(const float4*)(qk + baseA + (size_t)m * strideA + kp);
        unsigned* dst = &As[m * QG_LD + kp];
        dst[0] = f2tf(v.x); dst[1] = f2tf(v.y);
        dst[2] = f2tf(v.z); dst[3] = f2tf(v.w);
    }

    CP_WAIT(0);
    __syncthreads();

#pragma unroll
    for (int k8 = 0; k8 < 64; k8 += 8) {
        unsigned a[4][4], b2[4][2];
#pragma unroll
        for (int mi = 0; mi < 4; mi++) {
            int r = wm + mi * 16 + grp;
            a[mi][0] = As[r * QG_LD + k8 + tig];
            a[mi][1] = As[(r + 8) * QG_LD + k8 + tig];
            a[mi][2] = As[r * QG_LD + k8 + tig + 4];
            a[mi][3] = As[(r + 8) * QG_LD + k8 + tig + 4];
        }
#pragma unroll
        for (int ni = 0; ni < 4; ni++) {
            int n = wn + ni * 8 + grp;
            b2[ni][0] = Bs[n * QG_LD + k8 + tig];
            b2[ni][1] = Bs[n * QG_LD + k8 + tig + 4];
        }
#pragma unroll
        for (int mi = 0; mi < 4; mi++)
#pragma unroll
            for (int ni = 0; ni < 4; ni++)
                mma_tf32(acc[mi][ni], a[mi], b2[ni]);
    }

#pragma unroll
    for (int mi = 0; mi < 4; mi++) {
        int r = wm + mi * 16 + grp;
#pragma unroll
        for (int ni = 0; ni < 4; ni++) {
            int n = wn + ni * 8 + tig * 2;
            float2 v0, v1;
            v0.x = acc[mi][ni][0]; v0.y = acc[mi][ni][1];
            v1.x = acc[mi][ni][2]; v1.y = acc[mi][ni][3];
            *(float2*)(out + baseO + (size_t)r * strideO + n) = v0;
            *(float2*)(out + baseO + (size_t)(r + 8) * strideO + n) = v1;
        }
    }
}

// ---------------------------------------------------------------------------
extern "C" void kernel_launch(void* const* d_in, const int* in_sizes, int n_in,
                              void* d_out, int out_size) {
    const float* qk     = (const float*)d_in[0];
    const float* temb   = (const float*)d_in[1];
    const int*   pd     = (const int*)d_in[2];
    const float* w_dist = (const float*)d_in[3];
    const float* b_dist = (const float*)d_in[4];
    const float* w_time = (const float*)d_in[5];
    const float* b_time = (const float*)d_in[6];
    const float* w_out  = (const float*)d_in[7];
    const float* b_out  = (const float*)d_in[8];
    float* out = (float*)d_out;

    const int rg_smem = 3 * (RG_AS + RG_BS) * 4;   // 98,304 B (2 blk/SM)
    const int qg_smem = 2 * QG_SZ * 4;             // 69,632 B (2+ blk/SM)
    cudaFuncSetAttribute(k_rgemm_tc, cudaFuncAttributeMaxDynamicSharedMemorySize, rg_smem);
    cudaFuncSetAttribute(k_qkgemm_tc, cudaFuncAttributeMaxDynamicSharedMemorySize, qg_smem);

    k_prep<<<351, 512>>>(w_dist, b_dist, w_out, temb, w_time, b_time);
    k_act<<<NROW / 16 * 8, 256>>>(pd);                       // 16384 blocks
    k_rgemm_tc<<<dim3(Cc / 128, NROW / 128), 256, rg_smem>>>(b_out);
    k_qkgemm_tc<<<Bb * Hh * Tt * 2, 256, qg_smem>>>(qk, out);
}